// round 3
// baseline (speedup 1.0000x reference)
#include <cuda_runtime.h>
#include <math.h>

#define T_  512
#define B_  64
#define IN_ 1024
#define H_  1024
#define BH  (B_*H_)            // 65536
#define TBH ((size_t)T_*BH)
#define NBLK 192

// Scratch (static __device__ arrays per harness rules)
__device__ float g_X0[T_*B_*H_];     // precomputed input GEMM + biases (128 MB)
__device__ float g_h0[2][BH];        // h0 ping-pong
__device__ float g_part0[8][BH];     // layer0 K-split partials
__device__ float g_part1[16][BH];    // layer1 K-split partials (K=2048 concat)

__device__ unsigned g_bar_count = 0;
__device__ unsigned g_bar_epoch = 0;

__device__ __forceinline__ void grid_barrier(){
    __syncthreads();
    if (threadIdx.x == 0){
        volatile unsigned* ep = &g_bar_epoch;
        unsigned e = *ep;                    // read BEFORE arriving (monotonic epoch)
        __threadfence();
        if (atomicAdd(&g_bar_count, 1u) == NBLK - 1u){
            g_bar_count = 0;
            __threadfence();
            atomicAdd(&g_bar_epoch, 1u);
        } else {
            while (*ep == e) { __nanosleep(32); }
        }
        __threadfence();
    }
    __syncthreads();
}

__device__ __forceinline__ void ffma2(unsigned long long &acc, unsigned long long a, unsigned long long b){
    asm("fma.rn.f32x2 %0, %1, %2, %0;" : "+l"(acc) : "l"(a), "l"(b));
}
__device__ __forceinline__ float lo32(unsigned long long u){ return __uint_as_float((unsigned)u); }
__device__ __forceinline__ float hi32(unsigned long long u){ return __uint_as_float((unsigned)(u>>32)); }

// Tile GEMM core: out[64 x 128] += A[64 x Ktot] * W[128 x Ktot]^T
// acc[i][c] packs rows (m0+2i, m0+2i+1) for col j0+c.
__device__ __forceinline__ void gemm_core(const float* __restrict__ A, int ldA,
                                          const float* __restrict__ W, int ldW,
                                          int Ktot, unsigned long long (&acc)[4][4])
{
    __shared__ __align__(16) float  sA[2][16][66];   // [k][row], padded
    __shared__ __align__(16) float2 sW[2][16][128];  // [k][j] duplicated {w,w}

    const int t    = threadIdx.x;
    const int arow = t >> 2, aq = t & 3;      // A staging: 64 rows x 4 quads
    const int wjj  = t >> 1, wh = t & 1;      // W staging: 128 rows x 2 halves
    const int lane = t & 31, warp = t >> 5;
    const int m0 = (warp >> 2)*32 + (lane >> 3)*8;   // 2 warp-rows x 4 bgroups
    const int j0 = (warp & 3)*32 + (lane & 7)*4;     // 4 warp-cols x 8 jgroups

    auto stage = [&](int buf, int kk){
        float4 v = *reinterpret_cast<const float4*>(A + arow*ldA + kk + 4*aq);
        sA[buf][4*aq+0][arow] = v.x;
        sA[buf][4*aq+1][arow] = v.y;
        sA[buf][4*aq+2][arow] = v.z;
        sA[buf][4*aq+3][arow] = v.w;
        const float* wp = W + wjj*ldW + kk + 8*wh;
        float4 w0 = *reinterpret_cast<const float4*>(wp);
        float4 w1 = *reinterpret_cast<const float4*>(wp + 4);
        sW[buf][8*wh+0][wjj] = make_float2(w0.x, w0.x);
        sW[buf][8*wh+1][wjj] = make_float2(w0.y, w0.y);
        sW[buf][8*wh+2][wjj] = make_float2(w0.z, w0.z);
        sW[buf][8*wh+3][wjj] = make_float2(w0.w, w0.w);
        sW[buf][8*wh+4][wjj] = make_float2(w1.x, w1.x);
        sW[buf][8*wh+5][wjj] = make_float2(w1.y, w1.y);
        sW[buf][8*wh+6][wjj] = make_float2(w1.z, w1.z);
        sW[buf][8*wh+7][wjj] = make_float2(w1.w, w1.w);
    };

    const int nIter = Ktot >> 4;
    stage(0, 0);
    __syncthreads();
    for (int it = 0; it < nIter; ++it){
        const int buf = it & 1;
        if (it + 1 < nIter) stage(buf ^ 1, (it + 1) << 4);
        #pragma unroll
        for (int kc = 0; kc < 16; ++kc){
            unsigned long long hp[4], wp2[4];
            #pragma unroll
            for (int i = 0; i < 4; ++i)
                hp[i] = *reinterpret_cast<const unsigned long long*>(&sA[buf][kc][m0 + 2*i]);
            #pragma unroll
            for (int c = 0; c < 4; ++c)
                wp2[c] = *reinterpret_cast<const unsigned long long*>(&sW[buf][kc][j0 + c]);
            #pragma unroll
            for (int i = 0; i < 4; ++i)
                #pragma unroll
                for (int c = 0; c < 4; ++c)
                    ffma2(acc[i][c], hp[i], wp2[c]);
        }
        __syncthreads();
    }
}

// ---- Phase 1: X0[i][j] = input[i][:] . W_ih0[j][:] + b_ih0[j] + b_hh0[j] ----
__global__ void __launch_bounds__(256) k_precompute(const float* __restrict__ input,
        const float* __restrict__ Wih0, const float* __restrict__ bih0, const float* __restrict__ bhh0)
{
    const int colt = blockIdx.x & 7;        // 8 col tiles of 128
    const int rowt = blockIdx.x >> 3;       // 512 row tiles of 64
    const float* A = input + (size_t)rowt * 64 * IN_;
    const float* W = Wih0 + (size_t)colt * 128 * IN_;

    unsigned long long acc[4][4] = {};
    gemm_core(A, IN_, W, IN_, IN_, acc);

    const int t = threadIdx.x, lane = t & 31, warp = t >> 5;
    const int m0 = (warp >> 2)*32 + (lane >> 3)*8;
    const int j0 = (warp & 3)*32 + (lane & 7)*4;
    const int jbase = colt*128 + j0;
    float bs[4];
    #pragma unroll
    for (int c = 0; c < 4; ++c) bs[c] = bih0[jbase+c] + bhh0[jbase+c];
    size_t rbase = ((size_t)rowt*64 + m0) * H_ + jbase;
    #pragma unroll
    for (int i = 0; i < 4; ++i){
        float4 vlo = make_float4(lo32(acc[i][0])+bs[0], lo32(acc[i][1])+bs[1],
                                 lo32(acc[i][2])+bs[2], lo32(acc[i][3])+bs[3]);
        float4 vhi = make_float4(hi32(acc[i][0])+bs[0], hi32(acc[i][1])+bs[1],
                                 hi32(acc[i][2])+bs[2], hi32(acc[i][3])+bs[3]);
        *reinterpret_cast<float4*>(&g_X0[rbase + (size_t)(2*i  )*H_]) = vlo;
        *reinterpret_cast<float4*>(&g_X0[rbase + (size_t)(2*i+1)*H_]) = vhi;
    }
}

// ---- Phase 2: persistent recurrence kernel. 192 blocks, all co-resident. ----
// Per step s: blocks 0..63 compute layer0 K-split partials (h0_{s-1} @ Whh0^T),
// blocks 64..191 compute layer1 partials for step s-1 (concat [h0_{s-1}|h1_{s-2}]).
// Then barrier, all blocks reduce+tanh, barrier.
__global__ void __launch_bounds__(256) k_persistent(
    const float* __restrict__ h0_in,        // h_0 [2,B,H]
    float* __restrict__ out,                // d_out
    const float* __restrict__ Whh0, const float* __restrict__ Wih1, const float* __restrict__ Whh1,
    const float* __restrict__ bih1, const float* __restrict__ bhh1)
{
    const int b = blockIdx.x;
    const int t = threadIdx.x;
    const float* h1_init = h0_in + BH;

    // init: h0_{-1} lives in buffer 1 (step 0 reads buffer (0+1)&1)
    for (int i = b*256 + t; i < BH; i += NBLK*256)
        g_h0[1][i] = h0_in[i];
    grid_barrier();

    for (int s = 0; s <= T_; ++s){
        const int pb = (s + 1) & 1;          // buffer holding h0_{s-1}

        // ---- GEMM phase ----
        const float* A = nullptr; const float* W = nullptr; float* P = nullptr;
        int colt = 0;
        bool active = false;
        if (b < 64){
            if (s < T_){
                colt = b & 7;
                const int kch = b >> 3;                     // 0..7
                A = g_h0[pb] + kch*128;
                W = Whh0 + (size_t)colt*128*H_ + kch*128;
                P = g_part0[kch];
                active = true;
            }
        } else {
            if (s >= 1){
                const int lb = b - 64;
                colt = lb & 7;
                const int kch = lb >> 3;                    // 0..15
                const int kg = kch * 128;
                if (kg < 1024){
                    A = g_h0[pb] + kg;
                    W = Wih1 + (size_t)colt*128*H_ + kg;
                } else {
                    const float* h1p = (s == 1) ? h1_init : (out + (size_t)(s-2)*BH);
                    A = h1p + (kg - 1024);
                    W = Whh1 + (size_t)colt*128*H_ + (kg - 1024);
                }
                P = g_part1[kch];
                active = true;
            }
        }

        if (active){
            unsigned long long acc[4][4] = {};
            gemm_core(A, H_, W, H_, 128, acc);
            const int lane = t & 31, warp = t >> 5;
            const int m0 = (warp >> 2)*32 + (lane >> 3)*8;
            const int j0 = (warp & 3)*32 + (lane & 7)*4;
            size_t base = (size_t)m0*H_ + colt*128 + j0;
            #pragma unroll
            for (int i = 0; i < 4; ++i){
                float4 vlo = make_float4(lo32(acc[i][0]), lo32(acc[i][1]), lo32(acc[i][2]), lo32(acc[i][3]));
                float4 vhi = make_float4(hi32(acc[i][0]), hi32(acc[i][1]), hi32(acc[i][2]), hi32(acc[i][3]));
                *reinterpret_cast<float4*>(&P[base + (size_t)(2*i  )*H_]) = vlo;
                *reinterpret_cast<float4*>(&P[base + (size_t)(2*i+1)*H_]) = vhi;
            }
        }
        grid_barrier();

        // ---- reduce + tanh phase ----
        {
            const bool L0 = (s < T_), L1 = (s >= 1);
            const int nA = L0 ? BH : 0;
            const int total = nA + (L1 ? BH : 0);
            for (int idx = b*256 + t; idx < total; idx += NBLK*256){
                if (idx < nA){
                    float v = g_X0[(size_t)s*BH + idx];
                    #pragma unroll
                    for (int p = 0; p < 8; ++p) v += g_part0[p][idx];
                    g_h0[s & 1][idx] = tanhf(v);
                } else {
                    const int e = idx - nA;
                    const int j = e & (H_ - 1);
                    float v = bih1[j] + bhh1[j];
                    #pragma unroll
                    for (int p = 0; p < 16; ++p) v += g_part1[p][e];
                    out[(size_t)(s-1)*BH + e] = tanhf(v);
                }
            }
        }
        grid_barrier();
    }

    // final h_n: h_n[0] = h0_{T-1}, h_n[1] = h1_{T-1} (already in out[T-1])
    for (int i = b*256 + t; i < BH; i += NBLK*256){
        out[TBH + i]      = g_h0[(T_-1) & 1][i];
        out[TBH + BH + i] = out[(size_t)(T_-1)*BH + i];
    }
}

extern "C" void kernel_launch(void* const* d_in, const int* in_sizes, int n_in,
                              void* d_out, int out_size)
{
    const float* input = (const float*)d_in[0];
    const float* h0in  = (const float*)d_in[1];   // [2, B, H]
    const float* Wih0  = (const float*)d_in[2];
    const float* bih0  = (const float*)d_in[3];
    const float* Whh0  = (const float*)d_in[4];
    const float* bhh0  = (const float*)d_in[5];
    const float* Wih1  = (const float*)d_in[6];
    const float* bih1  = (const float*)d_in[7];
    const float* Whh1  = (const float*)d_in[8];
    const float* bhh1  = (const float*)d_in[9];
    float* out = (float*)d_out;

    k_precompute<<<4096, 256>>>(input, Wih0, bih0, bhh0);
    k_persistent<<<NBLK, 256>>>(h0in, out, Whh0, Wih1, Whh1, bih1, bhh1);
}

// round 4
// speedup vs baseline: 2.0527x; 2.0527x over previous
#include <cuda_runtime.h>
#include <math.h>

#define T_ 512
#define H_ 1024
#define BH 65536
#define TBH ((size_t)T_*BH)
#define NBLK 148
#define NTHR 256
typedef unsigned long long ull;

__device__ float g_h0[2][BH];
__device__ float g_p0[8][BH];
__device__ float g_px[8][BH];
__device__ float g_p1[16][BH];
__device__ float g_b0[H_], g_b1[H_];
__device__ unsigned g_cnt = 0, g_ep = 0;

__device__ __forceinline__ void gbar(){
    __syncthreads();
    if (threadIdx.x == 0){
        volatile unsigned* ep = &g_ep;
        unsigned e = *ep;                  // read BEFORE arriving (monotonic epoch)
        __threadfence();
        if (atomicAdd(&g_cnt, 1u) == NBLK - 1u){
            g_cnt = 0; __threadfence(); atomicAdd(&g_ep, 1u);
        } else {
            while (*ep == e) __nanosleep(64);
        }
        __threadfence();
    }
    __syncthreads();
}

__device__ __forceinline__ void ffma2(ull &a, ull x, ull y){
    asm("fma.rn.f32x2 %0, %1, %2, %0;" : "+l"(a) : "l"(x), "l"(y));
}

// smem: sW = 128k x 256j floats (128KB), sA = 64row x 128k dup float2 (64KB)
#define SMEM_BYTES (128*256*4 + 64*128*8)

__global__ void __launch_bounds__(NTHR, 1) k_rnn(
    const float* __restrict__ input, const float* __restrict__ h0_in,
    const float* __restrict__ Wih0, const float* __restrict__ bih0,
    const float* __restrict__ Whh0, const float* __restrict__ bhh0,
    const float* __restrict__ Wih1, const float* __restrict__ bih1,
    const float* __restrict__ Whh1, const float* __restrict__ bhh1,
    float* __restrict__ out)
{
    extern __shared__ float sm[];
    float*  sW = sm;                        // sW[k*256 + j] = W[(j0+j)][k0+k]
    float2* sA = (float2*)(sm + 128*256);   // sA[row*128 + k] = {a,a}
    const int bid = blockIdx.x, t = threadIdx.x;
    const int l = t & 31, w = t >> 5;

    // ---- fixed task per block ----
    // 0..31: L0 (h0@Whh0^T)  32..63: X0 (input_s@Wih0^T)  64..127: L1 (concat)
    int kind = -1, j0 = 0, k0 = 0;
    const float* Wsrc = Whh0; float* P = g_p0[0];
    if (bid < 32){       kind = 0; j0 = (bid >> 3)*256; k0 = (bid & 7)*128; Wsrc = Whh0; P = g_p0[bid & 7]; }
    else if (bid < 64){  int x = bid - 32; kind = 1; j0 = (x >> 3)*256; k0 = (x & 7)*128; Wsrc = Wih0; P = g_px[x & 7]; }
    else if (bid < 128){ int lt = bid - 64; int kc = lt & 15; int kg = kc*128; j0 = (lt >> 4)*256; P = g_p1[kc];
                         if (kg < 1024){ kind = 2; k0 = kg; Wsrc = Wih1; }
                         else          { kind = 3; k0 = kg - 1024; Wsrc = Whh1; } }

    // ---- stage W ONCE (lanes vary j -> conflict-free STS) ----
    if (kind >= 0){
        for (int u = t; u < 8192; u += NTHR){
            int j = u & 255, q = u >> 8;    // q: k-quad 0..31
            float4 v = *(const float4*)&Wsrc[(size_t)(j0 + j)*1024 + k0 + 4*q];
            sW[(4*q+0)*256 + j] = v.x;
            sW[(4*q+1)*256 + j] = v.y;
            sW[(4*q+2)*256 + j] = v.z;
            sW[(4*q+3)*256 + j] = v.w;
        }
    }

    // ---- init: bias sums + h0 seed (h0_{-1} in buffer 1) ----
    const int gid = bid*NTHR + t, gs = NBLK*NTHR;
    for (int j = gid; j < H_; j += gs){ g_b0[j] = bih0[j] + bhh0[j]; g_b1[j] = bih1[j] + bhh1[j]; }
    for (int i = gid; i < BH; i += gs) g_h0[1][i] = h0_in[i];
    gbar();

    for (int s = 0; s <= T_; ++s){
        const float* h0p = g_h0[(s + 1) & 1];            // h0_{s-1}
        const bool act = (kind < 0) ? false : (kind <= 1 ? (s < T_) : (s >= 1));

        if (act){
            const float* Asrc;
            if (kind == 0 || kind == 2) Asrc = h0p + k0;
            else if (kind == 1)         Asrc = input + (size_t)s*BH + k0;
            else                        Asrc = ((s == 1) ? (h0_in + BH) : (out + (size_t)(s-2)*BH)) + k0;

            // stage A (coalesced LDG, conflict-free dup STS)
            for (int u = t; u < 2048; u += NTHR){
                int row = u >> 5, q = u & 31;
                float4 v = *(const float4*)&Asrc[(size_t)row*1024 + 4*q];
                sA[row*128 + 4*q + 0] = make_float2(v.x, v.x);
                sA[row*128 + 4*q + 1] = make_float2(v.y, v.y);
                sA[row*128 + 4*q + 2] = make_float2(v.z, v.z);
                sA[row*128 + 4*q + 3] = make_float2(v.w, v.w);
            }
            __syncthreads();

            ull acc[8][4] = {};
            #pragma unroll 2
            for (int k = 0; k < 128; k += 2){
                ull a0[8], a1[8], w0[4], w1[4];
                #pragma unroll
                for (int r = 0; r < 8; ++r){
                    ulonglong2 av = *(const ulonglong2*)&sA[(8*w + r)*128 + k];
                    a0[r] = av.x; a1[r] = av.y;      // broadcast LDS.128: 2 k-steps
                }
                #pragma unroll
                for (int c = 0; c < 4; ++c){
                    w0[c] = *(const ull*)&sW[k*256 + 2*l + 64*c];
                    w1[c] = *(const ull*)&sW[(k+1)*256 + 2*l + 64*c];
                }
                #pragma unroll
                for (int r = 0; r < 8; ++r)
                    #pragma unroll
                    for (int c = 0; c < 4; ++c){
                        ffma2(acc[r][c], a0[r], w0[c]);
                        ffma2(acc[r][c], a1[r], w1[c]);
                    }
            }
            #pragma unroll
            for (int r = 0; r < 8; ++r){
                const int row = 8*w + r;
                #pragma unroll
                for (int c = 0; c < 4; ++c)
                    *(ull*)&P[(size_t)row*1024 + j0 + 2*l + 64*c] = acc[r][c];
            }
        }
        gbar();

        // ---- reduce + tanh (float4 over L2-resident partials) ----
        for (int i = gid; i < 2*(BH/4); i += gs){
            if (i < BH/4){
                if (s < T_){
                    float4 v = *(const float4*)&g_b0[(i & 255)*4];
                    #pragma unroll
                    for (int p = 0; p < 8; ++p){
                        float4 a = *(const float4*)&g_p0[p][i*4];
                        float4 b = *(const float4*)&g_px[p][i*4];
                        v.x += a.x + b.x; v.y += a.y + b.y;
                        v.z += a.z + b.z; v.w += a.w + b.w;
                    }
                    float4 r = make_float4(tanhf(v.x), tanhf(v.y), tanhf(v.z), tanhf(v.w));
                    *(float4*)&g_h0[s & 1][i*4] = r;
                }
            } else if (s >= 1){
                int e = i - BH/4;
                float4 v = *(const float4*)&g_b1[(e & 255)*4];
                #pragma unroll
                for (int p = 0; p < 16; ++p){
                    float4 a = *(const float4*)&g_p1[p][e*4];
                    v.x += a.x; v.y += a.y; v.z += a.z; v.w += a.w;
                }
                float4 r = make_float4(tanhf(v.x), tanhf(v.y), tanhf(v.z), tanhf(v.w));
                *(float4*)&out[(size_t)(s-1)*BH + e*4] = r;
            }
        }
        gbar();
    }

    // h_n[0] = h0_{T-1} (buffer (T_-1)&1), h_n[1] = h1_{T-1} (= out[T-1])
    for (int i = gid; i < BH; i += gs){
        out[TBH + i]      = g_h0[(T_ - 1) & 1][i];
        out[TBH + BH + i] = out[(size_t)(T_ - 1)*BH + i];
    }
}

extern "C" void kernel_launch(void* const* d_in, const int* in_sizes, int n_in,
                              void* d_out, int out_size)
{
    const float* input = (const float*)d_in[0];
    const float* h0in  = (const float*)d_in[1];
    const float* Wih0  = (const float*)d_in[2];
    const float* bih0  = (const float*)d_in[3];
    const float* Whh0  = (const float*)d_in[4];
    const float* bhh0  = (const float*)d_in[5];
    const float* Wih1  = (const float*)d_in[6];
    const float* bih1  = (const float*)d_in[7];
    const float* Whh1  = (const float*)d_in[8];
    const float* bhh1  = (const float*)d_in[9];
    float* out = (float*)d_out;

    cudaFuncSetAttribute(k_rnn, cudaFuncAttributeMaxDynamicSharedMemorySize, SMEM_BYTES);
    k_rnn<<<NBLK, NTHR, SMEM_BYTES>>>(input, h0in, Wih0, bih0, Whh0, bhh0,
                                      Wih1, bih1, Whh1, bhh1, out);
}

// round 8
// speedup vs baseline: 3.0420x; 1.4820x over previous
#include <cuda_runtime.h>
#include <cuda_bf16.h>
#include <math.h>

#define T_ 512
#define H_ 1024
#define BH 65536
#define TBH ((size_t)T_*BH)
#define NBLK 128
#define NTHR 256
typedef unsigned long long ull;
typedef unsigned int u32;

__device__ float g_h0[2][BH];
__device__ float g_p0[8][BH];
__device__ float g_px[8][BH];
__device__ float g_p1[16][BH];
__device__ float g_b0[H_], g_b1[H_];
__device__ unsigned g_cnt = 0, g_ep = 0;

__device__ __forceinline__ void gbar(){
    __syncthreads();
    if (threadIdx.x == 0){
        volatile unsigned* ep = &g_ep;
        unsigned e = *ep;                  // read BEFORE arriving (monotonic epoch)
        __threadfence();
        if (atomicAdd(&g_cnt, 1u) == NBLK - 1u){
            g_cnt = 0; __threadfence(); atomicAdd(&g_ep, 1u);
        } else {
            while (*ep == e) __nanosleep(32);
        }
        __threadfence();
    }
    __syncthreads();
}

__device__ __forceinline__ u32 smaddr(const void* p){
    u32 a; asm("{ .reg .u64 t; cvta.to.shared.u64 t, %1; cvt.u32.u64 %0, t; }" : "=r"(a) : "l"(p));
    return a;
}

__device__ __forceinline__ void split4(float4 v, ull &hp, ull &lp){
    __nv_bfloat16 h0=__float2bfloat16_rn(v.x), h1=__float2bfloat16_rn(v.y),
                  h2=__float2bfloat16_rn(v.z), h3=__float2bfloat16_rn(v.w);
    __nv_bfloat16 l0=__float2bfloat16_rn(v.x-__bfloat162float(h0)),
                  l1=__float2bfloat16_rn(v.y-__bfloat162float(h1)),
                  l2=__float2bfloat16_rn(v.z-__bfloat162float(h2)),
                  l3=__float2bfloat16_rn(v.w-__bfloat162float(h3));
    hp = (ull)__bfloat16_as_ushort(h0) | ((ull)__bfloat16_as_ushort(h1)<<16)
       | ((ull)__bfloat16_as_ushort(h2)<<32) | ((ull)__bfloat16_as_ushort(h3)<<48);
    lp = (ull)__bfloat16_as_ushort(l0) | ((ull)__bfloat16_as_ushort(l1)<<16)
       | ((ull)__bfloat16_as_ushort(l2)<<32) | ((ull)__bfloat16_as_ushort(l3)<<48);
}

__device__ __forceinline__ void ldsm4(u32 &r0,u32 &r1,u32 &r2,u32 &r3, u32 a){
    asm volatile("ldmatrix.sync.aligned.m8n8.x4.shared.b16 {%0,%1,%2,%3}, [%4];"
                 : "=r"(r0),"=r"(r1),"=r"(r2),"=r"(r3) : "r"(a));
}
__device__ __forceinline__ void mma16816(float* d, u32 a0,u32 a1,u32 a2,u32 a3, u32 b0,u32 b1){
    asm volatile("mma.sync.aligned.m16n8k16.row.col.f32.bf16.bf16.f32 "
                 "{%0,%1,%2,%3}, {%4,%5,%6,%7}, {%8,%9}, {%0,%1,%2,%3};"
                 : "+f"(d[0]),"+f"(d[1]),"+f"(d[2]),"+f"(d[3])
                 : "r"(a0),"r"(a1),"r"(a2),"r"(a3),"r"(b0),"r"(b1));
}

// smem: W hi/lo 256x128 bf16 swizzled (64KB each), A hi/lo 64x128 bf16 (16KB each)
#define SMEM_BYTES (2*65536 + 2*16384)

__global__ void __launch_bounds__(NTHR, 1) k_rnn(
    const float* __restrict__ input, const float* __restrict__ h0_in,
    const float* __restrict__ Wih0, const float* __restrict__ bih0,
    const float* __restrict__ Whh0, const float* __restrict__ bhh0,
    const float* __restrict__ Wih1, const float* __restrict__ bih1,
    const float* __restrict__ Whh1, const float* __restrict__ bhh1,
    float* __restrict__ out)
{
    extern __shared__ char smch[];
    char* sWhi = smch;
    char* sWlo = smch + 65536;
    char* sAhi = smch + 131072;
    char* sAlo = smch + 147456;

    const int bid = blockIdx.x, t = threadIdx.x;
    const int l = t & 31, w = t >> 5;

    // ---- task decode: 0..31 L0, 32..63 X0, 64..127 L1 ----
    int kind, j0, k0;
    const float* Wsrc; float* P;
    if (bid < 32){       kind = 0; j0 = (bid >> 3)*256; k0 = (bid & 7)*128; Wsrc = Whh0; P = g_p0[bid & 7]; }
    else if (bid < 64){  int x = bid - 32; kind = 1; j0 = (x >> 3)*256; k0 = (x & 7)*128; Wsrc = Wih0; P = g_px[x & 7]; }
    else {               int lt = bid - 64; int kc = lt & 15; int kg = kc*128; j0 = (lt >> 4)*256; P = g_p1[kc];
                         if (kg < 1024){ kind = 2; k0 = kg; Wsrc = Wih1; }
                         else          { kind = 3; k0 = kg - 1024; Wsrc = Whh1; } }

    // ---- stage W hi/lo ONCE (XOR-swizzled rows of 256B) ----
    for (int u = t; u < 256*32; u += NTHR){
        int j = u >> 5, kq = u & 31;
        float4 v = *(const float4*)&Wsrc[(size_t)(j0 + j)*1024 + k0 + 4*kq];
        ull hp, lp; split4(v, hp, lp);
        int off = j*256 + ((kq*8) ^ ((j & 7) << 4));
        *(ull*)(sWhi + off) = hp; *(ull*)(sWlo + off) = lp;
    }

    // ---- init biases + h0 seed ----
    const int gid = bid*NTHR + t, gs = NBLK*NTHR;
    for (int j = gid; j < H_; j += gs){ g_b0[j] = bih0[j] + bhh0[j]; g_b1[j] = bih1[j] + bhh1[j]; }
    for (int i = gid; i < BH; i += gs) g_h0[1][i] = h0_in[i];
    gbar();

    // per-lane ldmatrix geometry (all NON-trans: B is N x K row-major = .col operand)
    const int r   = l & 7;
    const u32 r16 = (u32)r << 4;
    const int halfm = (l >> 3) & 1;      // A: m-half | B: k-half
    const int kh    = l >> 4;            // A: k-half | B: n-half
    const u32 aWhi = smaddr(sWhi), aWlo = smaddr(sWlo);
    const u32 aAhi = smaddr(sAhi), aAlo = smaddr(sAlo);
    u32 aOff[4], bOff[2];
    #pragma unroll
    for (int mt = 0; mt < 4; ++mt) aOff[mt] = (u32)(mt*16 + halfm*8 + r) * 256;
    #pragma unroll
    for (int nt2 = 0; nt2 < 2; ++nt2) bOff[nt2] = (u32)(w*32 + nt2*16 + kh*8 + r) * 256;
    const u32 aKl = (u32)kh << 4;        // A lane k-byte offset (k+8)
    const u32 bKl = (u32)halfm << 4;     // B lane k-byte offset (k+8)

    for (int s = 0; s <= T_; ++s){
        const float* h0p = g_h0[(s + 1) & 1];
        const bool act = (kind <= 1) ? (s < T_) : (s >= 1);

        if (act){
            const float* Asrc;
            if (kind == 0 || kind == 2) Asrc = h0p + k0;
            else if (kind == 1)         Asrc = input + (size_t)s*BH + k0;
            else                        Asrc = ((s == 1) ? (h0_in + BH) : (out + (size_t)(s-2)*BH)) + k0;

            // stage A hi/lo (64 rows x 128 k)
            for (int u = t; u < 64*32; u += NTHR){
                int rr = u >> 5, kq = u & 31;
                float4 v = *(const float4*)&Asrc[(size_t)rr*1024 + 4*kq];
                ull hp, lp; split4(v, hp, lp);
                int off = rr*256 + ((kq*8) ^ ((rr & 7) << 4));
                *(ull*)(sAhi + off) = hp; *(ull*)(sAlo + off) = lp;
            }
            __syncthreads();

            float acc[4][4][4];
            #pragma unroll
            for (int i = 0; i < 4; ++i)
                #pragma unroll
                for (int j = 0; j < 4; ++j)
                    #pragma unroll
                    for (int q = 0; q < 4; ++q) acc[i][j][q] = 0.f;

            #pragma unroll
            for (int pass = 0; pass < 3; ++pass){
                const u32 aB = (pass == 1) ? aAlo : aAhi;
                const u32 bB = (pass == 2) ? aWlo : aWhi;
                #pragma unroll
                for (int ks = 0; ks < 8; ++ks){
                    u32 a[4][4], b[2][4];
                    #pragma unroll
                    for (int mt = 0; mt < 4; ++mt)
                        ldsm4(a[mt][0], a[mt][1], a[mt][2], a[mt][3],
                              aB + aOff[mt] + (((u32)(ks*32) + aKl) ^ r16));
                    #pragma unroll
                    for (int nt2 = 0; nt2 < 2; ++nt2)
                        ldsm4(b[nt2][0], b[nt2][1], b[nt2][2], b[nt2][3],
                              bB + bOff[nt2] + (((u32)(ks*32) + bKl) ^ r16));
                    #pragma unroll
                    for (int mt = 0; mt < 4; ++mt)
                        #pragma unroll
                        for (int nt2 = 0; nt2 < 2; ++nt2){
                            mma16816(acc[mt][2*nt2],   a[mt][0],a[mt][1],a[mt][2],a[mt][3], b[nt2][0], b[nt2][1]);
                            mma16816(acc[mt][2*nt2+1], a[mt][0],a[mt][1],a[mt][2],a[mt][3], b[nt2][2], b[nt2][3]);
                        }
                }
            }

            // epilogue: d-frag -> partials (row-major, float2 stores)
            const int erow = l >> 2, ecol = (l & 3)*2;
            #pragma unroll
            for (int mt = 0; mt < 4; ++mt)
                #pragma unroll
                for (int nt = 0; nt < 4; ++nt){
                    const int row = mt*16 + erow;
                    const int col = j0 + w*32 + nt*8 + ecol;
                    *(float2*)&P[(size_t)row*1024 + col]      = make_float2(acc[mt][nt][0], acc[mt][nt][1]);
                    *(float2*)&P[(size_t)(row+8)*1024 + col]  = make_float2(acc[mt][nt][2], acc[mt][nt][3]);
                }
        }
        gbar();

        // ---- reduce + tanh ----
        for (int i = gid; i < 2*(BH/4); i += gs){
            if (i < BH/4){
                if (s < T_){
                    float4 v = *(const float4*)&g_b0[(i & 255)*4];
                    #pragma unroll
                    for (int p = 0; p < 8; ++p){
                        float4 a = *(const float4*)&g_p0[p][i*4];
                        float4 b = *(const float4*)&g_px[p][i*4];
                        v.x += a.x + b.x; v.y += a.y + b.y;
                        v.z += a.z + b.z; v.w += a.w + b.w;
                    }
                    *(float4*)&g_h0[s & 1][i*4] =
                        make_float4(tanhf(v.x), tanhf(v.y), tanhf(v.z), tanhf(v.w));
                }
            } else if (s >= 1){
                int e = i - BH/4;
                float4 v = *(const float4*)&g_b1[(e & 255)*4];
                #pragma unroll
                for (int p = 0; p < 16; ++p){
                    float4 a = *(const float4*)&g_p1[p][e*4];
                    v.x += a.x; v.y += a.y; v.z += a.z; v.w += a.w;
                }
                *(float4*)&out[(size_t)(s-1)*BH + e*4] =
                    make_float4(tanhf(v.x), tanhf(v.y), tanhf(v.z), tanhf(v.w));
            }
        }
        gbar();
    }

    for (int i = gid; i < BH; i += gs){
        out[TBH + i]      = g_h0[(T_ - 1) & 1][i];
        out[TBH + BH + i] = out[(size_t)(T_ - 1)*BH + i];
    }
}

extern "C" void kernel_launch(void* const* d_in, const int* in_sizes, int n_in,
                              void* d_out, int out_size)
{
    const float* input = (const float*)d_in[0];
    const float* h0in  = (const float*)d_in[1];
    const float* Wih0  = (const float*)d_in[2];
    const float* bih0  = (const float*)d_in[3];
    const float* Whh0  = (const float*)d_in[4];
    const float* bhh0  = (const float*)d_in[5];
    const float* Wih1  = (const float*)d_in[6];
    const float* bih1  = (const float*)d_in[7];
    const float* Whh1  = (const float*)d_in[8];
    const float* bhh1  = (const float*)d_in[9];
    float* out = (float*)d_out;

    cudaFuncSetAttribute(k_rnn, cudaFuncAttributeMaxDynamicSharedMemorySize, SMEM_BYTES);
    k_rnn<<<NBLK, NTHR, SMEM_BYTES>>>(input, h0in, Wih0, bih0, Whh0, bhh0,
                                      Wih1, bih1, Whh1, bhh1, out);
}